// round 6
// baseline (speedup 1.0000x reference)
#include <cuda_runtime.h>
#include <math.h>
#include <stdint.h>

#define TSEQ   2048
#define BATCH  2
#define CDIM   1024
#define NHEAD  16
#define HD     64
#define WIN    256
#define MROWS  (BATCH*TSEQ)   /* 4096 */

// Scratch (allocation-free rule: __device__ globals)
static __device__ float g_q[(size_t)MROWS*CDIM];
static __device__ float g_k[(size_t)MROWS*CDIM];
static __device__ float g_v[(size_t)MROWS*CDIM];
static __device__ float g_y[(size_t)MROWS*CDIM];
static __device__ float g_xt[(size_t)MROWS*CDIM];      // tf32-rounded X
static __device__ float g_wt[4][(size_t)CDIM*CDIM];    // tf32-rounded weights

// ===========================================================================
// Common PTX helpers
// ===========================================================================
__device__ __forceinline__ uint32_t smem_u32(const void* p) {
    uint32_t a;
    asm("{ .reg .u64 t; cvta.to.shared.u64 t, %1; cvt.u32.u64 %0, t; }" : "=r"(a) : "l"(p));
    return a;
}
__device__ __forceinline__ void cp_async16(uint32_t s, const void* g) {
    asm volatile("cp.async.cg.shared.global [%0], [%1], 16;" :: "r"(s), "l"(g) : "memory");
}
__device__ __forceinline__ void cp_commit() {
    asm volatile("cp.async.commit_group;" ::: "memory");
}
template <int N_>
__device__ __forceinline__ void cp_wait() {
    asm volatile("cp.async.wait_group %0;" :: "n"(N_) : "memory");
}
__device__ __forceinline__ uint32_t to_tf32_bits(float x) {
    uint32_t y;
    asm("cvt.rna.tf32.f32 %0, %1;" : "=r"(y) : "f"(x));
    return y;
}
__device__ __forceinline__ float to_tf32f(float x) {
    return __uint_as_float(to_tf32_bits(x));
}
__device__ __forceinline__ void mma_tf32(float* c, const uint32_t* a, const uint32_t* b) {
    asm volatile(
        "mma.sync.aligned.m16n8k8.row.col.f32.tf32.tf32.f32 "
        "{%0,%1,%2,%3}, {%4,%5,%6,%7}, {%8,%9}, {%0,%1,%2,%3};"
        : "+f"(c[0]), "+f"(c[1]), "+f"(c[2]), "+f"(c[3])
        : "r"(a[0]), "r"(a[1]), "r"(a[2]), "r"(a[3]), "r"(b[0]), "r"(b[1]));
}

// ===========================================================================
// tf32 prepass: out[i] = tf32_round(in[i])
// ===========================================================================
__global__ void cvt_tf32_kernel(const float* __restrict__ in, float* __restrict__ out, int n4)
{
    int i = blockIdx.x * blockDim.x + threadIdx.x;
    if (i < n4) {
        float4 v = ((const float4*)in)[i];
        v.x = to_tf32f(v.x); v.y = to_tf32f(v.y);
        v.z = to_tf32f(v.z); v.w = to_tf32f(v.w);
        ((float4*)out)[i] = v;
    }
}

// ===========================================================================
// tf32 mma.sync GEMM: Y = X @ W + bias.  Inputs pre-rounded to tf32.
// CTA 128x128, BK=16, 8 warps (2M x 4N), warp tile 64x32, cp.async dbuf.
// round_out: 1 -> store tf32-rounded (outputs feeding later tf32 matmuls)
// ===========================================================================
#define BM 128
#define BN 128
#define BK 16
#define ASTR 20
#define BSTR 136   /* 136 mod 32 = 8 -> conflict-free B fragment loads */

__global__ __launch_bounds__(256, 2)
void gemm_mma_kernel(const float* __restrict__ X, const float* __restrict__ W,
                     const float* __restrict__ bias, float* __restrict__ Y,
                     int M, int N, int K, int round_out)
{
    __shared__ __align__(16) float As[2][BM * ASTR];
    __shared__ __align__(16) float Bs[2][BK * BSTR];

    const int tid  = threadIdx.x;
    const int wid  = tid >> 5;
    const int lane = tid & 31;
    const int wm   = wid & 1;
    const int wn   = wid >> 1;
    const int m0 = blockIdx.y * BM;
    const int n0 = blockIdx.x * BN;
    const int grp = lane >> 2;
    const int qid = lane & 3;

    float c[4][4][4];
#pragma unroll
    for (int i = 0; i < 4; i++)
#pragma unroll
        for (int j = 0; j < 4; j++)
#pragma unroll
            for (int r = 0; r < 4; r++) c[i][j][r] = 0.f;

    const int a_i0 = tid * 2, a_i1 = tid * 2 + 1;
    const int am[2] = { a_i0 >> 2, a_i1 >> 2 };
    const int as[2] = { a_i0 & 3,  a_i1 & 3 };
    const int bk_[2] = { a_i0 >> 5, a_i1 >> 5 };
    const int bs_[2] = { a_i0 & 31, a_i1 & 31 };

    const uint32_t sA[2] = { smem_u32(As[0]), smem_u32(As[1]) };
    const uint32_t sB[2] = { smem_u32(Bs[0]), smem_u32(Bs[1]) };

#define LOAD_STAGE(st, k0)                                                        \
    do {                                                                          \
        _Pragma("unroll")                                                         \
        for (int q = 0; q < 2; q++)                                               \
            cp_async16(sA[st] + (uint32_t)(am[q] * ASTR + as[q] * 4) * 4,         \
                       &X[(size_t)(m0 + am[q]) * K + (k0) + as[q] * 4]);          \
        _Pragma("unroll")                                                         \
        for (int q = 0; q < 2; q++)                                               \
            cp_async16(sB[st] + (uint32_t)(bk_[q] * BSTR + bs_[q] * 4) * 4,       \
                       &W[(size_t)((k0) + bk_[q]) * N + n0 + bs_[q] * 4]);        \
        cp_commit();                                                              \
    } while (0)

    LOAD_STAGE(0, 0);

    const int NIT = K / BK;
    for (int kt = 0; kt < NIT; kt++) {
        const int st = kt & 1;
        if (kt + 1 < NIT) {
            LOAD_STAGE(st ^ 1, (kt + 1) * BK);
            cp_wait<1>();
        } else {
            cp_wait<0>();
        }
        __syncthreads();

        const float* Ab = As[st];
        const float* Bb = Bs[st];
#pragma unroll
        for (int kk = 0; kk < 2; kk++) {
            const int kof = kk * 8;
            uint32_t af[4][4];
#pragma unroll
            for (int i = 0; i < 4; i++) {
                const int row = wm * 64 + i * 16 + grp;
                const int col = kof + qid;
                af[i][0] = __float_as_uint(Ab[row * ASTR + col]);
                af[i][1] = __float_as_uint(Ab[(row + 8) * ASTR + col]);
                af[i][2] = __float_as_uint(Ab[row * ASTR + col + 4]);
                af[i][3] = __float_as_uint(Ab[(row + 8) * ASTR + col + 4]);
            }
            uint32_t bf[4][2];
#pragma unroll
            for (int j = 0; j < 4; j++) {
                const int col = wn * 32 + j * 8 + grp;
                bf[j][0] = __float_as_uint(Bb[(kof + qid) * BSTR + col]);
                bf[j][1] = __float_as_uint(Bb[(kof + qid + 4) * BSTR + col]);
            }
#pragma unroll
            for (int i = 0; i < 4; i++)
#pragma unroll
                for (int j = 0; j < 4; j++)
                    mma_tf32(c[i][j], af[i], bf[j]);
        }
        __syncthreads();
    }

#pragma unroll
    for (int i = 0; i < 4; i++) {
        const int row = m0 + wm * 64 + i * 16 + grp;
#pragma unroll
        for (int j = 0; j < 4; j++) {
            const int col = n0 + wn * 32 + j * 8 + 2 * qid;
            const float b0 = bias[col], b1 = bias[col + 1];
            float o0 = c[i][j][0] + b0, o1 = c[i][j][1] + b1;
            float o2 = c[i][j][2] + b0, o3 = c[i][j][3] + b1;
            if (round_out) {
                o0 = to_tf32f(o0); o1 = to_tf32f(o1);
                o2 = to_tf32f(o2); o3 = to_tf32f(o3);
            }
            float2 v0 = { o0, o1 };
            float2 v1 = { o2, o3 };
            *(float2*)&Y[(size_t)row * N + col]       = v0;
            *(float2*)&Y[(size_t)(row + 8) * N + col] = v1;
        }
    }
#undef LOAD_STAGE
}

// ---------------------------------------------------------------------------
// Sliding-window flash attention, tf32 mma, mask-specialized tiles,
// V in separate buffer with early LDG issue.
// Inputs q/k/v pre-rounded to tf32; output written tf32-rounded.
// ---------------------------------------------------------------------------
#define QSTR 68
#define KSTR 68
#define VSTR 72    /* 72 mod 32 = 8 -> conflict-free V fragment loads */
#define SSTR 68
#define ATT_SMEM_F (64 * (QSTR + KSTR + VSTR + SSTR))

__global__ __launch_bounds__(256)
void attn_kernel(const float* __restrict__ qg, const float* __restrict__ kg,
                 const float* __restrict__ vg, float* __restrict__ yg)
{
    extern __shared__ __align__(16) float dsm[];
    float* qs = dsm;
    float* ks = qs + 64 * QSTR;
    float* vs = ks + 64 * KSTR;
    float* ss = vs + 64 * VSTR;
    __shared__ float mrow[64], lrow[64], arow[64];

    const int tid  = threadIdx.x;
    const int wid  = tid >> 5;
    const int lane = tid & 31;
    const int grp  = lane >> 2;
    const int qid  = lane & 3;
    const int mrow0 = (wid & 3) * 16;
    const int ncol0 = (wid >> 2) * 32;

    const int qt = blockIdx.x;
    const int h  = blockIdx.y;
    const int b  = blockIdx.z;
    const int q0 = qt * 64;
    const size_t base = ((size_t)b * TSEQ) * CDIM + (size_t)h * HD;

    for (int e = tid; e < 64 * 64; e += 256) {
        int r = e >> 6, d = e & 63;
        qs[r * QSTR + d] = qg[base + (size_t)(q0 + r) * CDIM + d];
    }
    if (tid < 64) { mrow[tid] = -INFINITY; lrow[tid] = 0.f; }

    float oacc[4][4];
#pragma unroll
    for (int j = 0; j < 4; j++)
#pragma unroll
        for (int r = 0; r < 4; r++) oacc[j][r] = 0.f;
    __syncthreads();

    const int kt_lo = (qt >= 4) ? (qt - 4) : 0;
    for (int kt = kt_lo; kt <= qt; kt++) {
        const int k0 = kt * 64;
        // K tile -> smem; V tile -> registers (latency hidden behind S mma)
        float vreg[16];
#pragma unroll
        for (int t = 0; t < 16; t++) {
            int e = t * 256 + tid;
            int r = e >> 6, d = e & 63;
            ks[r * KSTR + d] = kg[base + (size_t)(k0 + r) * CDIM + d];
            vreg[t]          = vg[base + (size_t)(k0 + r) * CDIM + d];
        }
        __syncthreads();

        // ---- S = Q K^T ----
        float sacc[4][4];
#pragma unroll
        for (int j = 0; j < 4; j++)
#pragma unroll
            for (int r = 0; r < 4; r++) sacc[j][r] = 0.f;
#pragma unroll
        for (int k8 = 0; k8 < 64; k8 += 8) {
            uint32_t af[4];
            const int ra = mrow0 + grp;
            af[0] = __float_as_uint(qs[ra * QSTR + k8 + qid]);
            af[1] = __float_as_uint(qs[(ra + 8) * QSTR + k8 + qid]);
            af[2] = __float_as_uint(qs[ra * QSTR + k8 + qid + 4]);
            af[3] = __float_as_uint(qs[(ra + 8) * QSTR + k8 + qid + 4]);
#pragma unroll
            for (int j = 0; j < 4; j++) {
                const int cn = ncol0 + j * 8 + grp;
                uint32_t bf[2];
                bf[0] = __float_as_uint(ks[cn * KSTR + k8 + qid]);
                bf[1] = __float_as_uint(ks[cn * KSTR + k8 + qid + 4]);
                mma_tf32(sacc[j], af, bf);
            }
        }

        // ---- mask/scale specialized per tile type ----
        const int r0 = mrow0 + grp;
        if (kt == qt) {              // causal edge: j <= i only
#pragma unroll
            for (int j = 0; j < 4; j++) {
                const int col = ncol0 + j * 8 + 2 * qid;
                const int d0 = r0 - col;          // i - j for (r0, col)
                ss[r0 * SSTR + col]           = (d0 >= 0) ? sacc[j][0] * 0.125f : -INFINITY;
                ss[r0 * SSTR + col + 1]       = (d0 >= 1) ? sacc[j][1] * 0.125f : -INFINITY;
                ss[(r0 + 8) * SSTR + col]     = (d0 >= -8) ? sacc[j][2] * 0.125f : -INFINITY;
                ss[(r0 + 8) * SSTR + col + 1] = (d0 >= -7) ? sacc[j][3] * 0.125f : -INFINITY;
            }
        } else if (kt == qt - 4) {   // window edge: i - j <= WIN
#pragma unroll
            for (int j = 0; j < 4; j++) {
                const int col = ncol0 + j * 8 + 2 * qid;
                const int d0 = (r0 + 256) - col;  // i - j
                ss[r0 * SSTR + col]           = (d0 <= WIN)     ? sacc[j][0] * 0.125f : -INFINITY;
                ss[r0 * SSTR + col + 1]       = (d0 - 1 <= WIN) ? sacc[j][1] * 0.125f : -INFINITY;
                ss[(r0 + 8) * SSTR + col]     = (d0 + 8 <= WIN) ? sacc[j][2] * 0.125f : -INFINITY;
                ss[(r0 + 8) * SSTR + col + 1] = (d0 + 7 <= WIN) ? sacc[j][3] * 0.125f : -INFINITY;
            }
        } else {                     // interior: fully valid
#pragma unroll
            for (int j = 0; j < 4; j++) {
                const int col = ncol0 + j * 8 + 2 * qid;
                ss[r0 * SSTR + col]           = sacc[j][0] * 0.125f;
                ss[r0 * SSTR + col + 1]       = sacc[j][1] * 0.125f;
                ss[(r0 + 8) * SSTR + col]     = sacc[j][2] * 0.125f;
                ss[(r0 + 8) * SSTR + col + 1] = sacc[j][3] * 0.125f;
            }
        }
        // store V registers to smem
#pragma unroll
        for (int t = 0; t < 16; t++) {
            int e = t * 256 + tid;
            int r = e >> 6, d = e & 63;
            vs[r * VSTR + d] = vreg[t];
        }
        __syncthreads();

        // ---- online softmax (P tf32-rounded into ss) ----
        {
            const int row = tid >> 2, seg = tid & 3;
            float* srow = ss + row * SSTR + seg * 16;
            float mloc = -INFINITY;
#pragma unroll
            for (int c2 = 0; c2 < 16; c2++) mloc = fmaxf(mloc, srow[c2]);
            mloc = fmaxf(mloc, __shfl_xor_sync(0xffffffffu, mloc, 1));
            mloc = fmaxf(mloc, __shfl_xor_sync(0xffffffffu, mloc, 2));
            const float mold = mrow[row];
            const float mnew = fmaxf(mold, mloc);
            const float al   = __expf(mold - mnew);
            float suml = 0.f;
#pragma unroll
            for (int c2 = 0; c2 < 16; c2++) {
                float p = __expf(srow[c2] - mnew);
                suml += p;
                srow[c2] = to_tf32f(p);
            }
            suml += __shfl_xor_sync(0xffffffffu, suml, 1);
            suml += __shfl_xor_sync(0xffffffffu, suml, 2);
            if (seg == 0) {
                mrow[row] = mnew;
                lrow[row] = lrow[row] * al + suml;
                arow[row] = al;
            }
        }
        __syncthreads();

        // ---- rescale O, O += P @ V ----
        {
            const float a_lo = arow[mrow0 + grp];
            const float a_hi = arow[mrow0 + grp + 8];
#pragma unroll
            for (int j = 0; j < 4; j++) {
                oacc[j][0] *= a_lo; oacc[j][1] *= a_lo;
                oacc[j][2] *= a_hi; oacc[j][3] *= a_hi;
            }
        }
#pragma unroll
        for (int k8 = 0; k8 < 64; k8 += 8) {
            uint32_t af[4];
            const int ra = mrow0 + grp;
            af[0] = __float_as_uint(ss[ra * SSTR + k8 + qid]);
            af[1] = __float_as_uint(ss[(ra + 8) * SSTR + k8 + qid]);
            af[2] = __float_as_uint(ss[ra * SSTR + k8 + qid + 4]);
            af[3] = __float_as_uint(ss[(ra + 8) * SSTR + k8 + qid + 4]);
#pragma unroll
            for (int j = 0; j < 4; j++) {
                const int cn = ncol0 + j * 8 + grp;
                uint32_t bf[2];
                bf[0] = __float_as_uint(vs[(k8 + qid) * VSTR + cn]);
                bf[1] = __float_as_uint(vs[(k8 + qid + 4) * VSTR + cn]);
                mma_tf32(oacc[j], af, bf);
            }
        }
        __syncthreads();
    }

    // epilogue: normalize, tf32-round (feeds out-projection GEMM), write
    {
        const int r0 = mrow0 + grp;
        const float inv_lo = 1.0f / lrow[r0];
        const float inv_hi = 1.0f / lrow[r0 + 8];
#pragma unroll
        for (int j = 0; j < 4; j++) {
            const int col = ncol0 + j * 8 + 2 * qid;
            float2 v0 = { to_tf32f(oacc[j][0] * inv_lo), to_tf32f(oacc[j][1] * inv_lo) };
            float2 v1 = { to_tf32f(oacc[j][2] * inv_hi), to_tf32f(oacc[j][3] * inv_hi) };
            *(float2*)&yg[base + (size_t)(q0 + r0) * CDIM + col]     = v0;
            *(float2*)&yg[base + (size_t)(q0 + r0 + 8) * CDIM + col] = v1;
        }
    }
}

// ---------------------------------------------------------------------------
extern "C" void kernel_launch(void* const* d_in, const int* in_sizes, int n_in,
                              void* d_out, int out_size)
{
    const float* x  = (const float*)d_in[0];
    const float* Wq = (const float*)d_in[1];
    const float* bq = (const float*)d_in[2];
    const float* Wk = (const float*)d_in[3];
    const float* bk = (const float*)d_in[4];
    const float* Wv = (const float*)d_in[5];
    const float* bv = (const float*)d_in[6];
    const float* Wo = (const float*)d_in[7];
    const float* bo = (const float*)d_in[8];
    float* out = (float*)d_out;
    (void)in_sizes; (void)n_in; (void)out_size;

    float *qp, *kp, *vp, *yp, *xtp, *wtp;
    cudaGetSymbolAddress((void**)&qp, g_q);
    cudaGetSymbolAddress((void**)&kp, g_k);
    cudaGetSymbolAddress((void**)&vp, g_v);
    cudaGetSymbolAddress((void**)&yp, g_y);
    cudaGetSymbolAddress((void**)&xtp, g_xt);
    cudaGetSymbolAddress((void**)&wtp, g_wt);
    float* wqT = wtp;
    float* wkT = wtp + (size_t)CDIM * CDIM;
    float* wvT = wtp + 2 * (size_t)CDIM * CDIM;
    float* woT = wtp + 3 * (size_t)CDIM * CDIM;

    const int ATT_SMEM = ATT_SMEM_F * (int)sizeof(float);
    cudaFuncSetAttribute(attn_kernel,
                         cudaFuncAttributeMaxDynamicSharedMemorySize, ATT_SMEM);

    // prepass: tf32-round X and weights
    const int NX4 = MROWS * CDIM / 4;
    const int NW4 = CDIM * CDIM / 4;
    cvt_tf32_kernel<<<(NX4 + 255) / 256, 256>>>(x,  xtp, NX4);
    cvt_tf32_kernel<<<(NW4 + 255) / 256, 256>>>(Wq, wqT, NW4);
    cvt_tf32_kernel<<<(NW4 + 255) / 256, 256>>>(Wk, wkT, NW4);
    cvt_tf32_kernel<<<(NW4 + 255) / 256, 256>>>(Wv, wvT, NW4);
    cvt_tf32_kernel<<<(NW4 + 255) / 256, 256>>>(Wo, woT, NW4);

    dim3 ggrid(CDIM / BN, MROWS / BM);
    gemm_mma_kernel<<<ggrid, 256>>>(xtp, wqT, bq, qp, MROWS, CDIM, CDIM, 1);
    gemm_mma_kernel<<<ggrid, 256>>>(xtp, wkT, bk, kp, MROWS, CDIM, CDIM, 1);
    gemm_mma_kernel<<<ggrid, 256>>>(xtp, wvT, bv, vp, MROWS, CDIM, CDIM, 1);

    attn_kernel<<<dim3(TSEQ / 64, NHEAD, BATCH), 256, ATT_SMEM>>>(qp, kp, vp, yp);

    gemm_mma_kernel<<<ggrid, 256>>>(yp, woT, bo, out, MROWS, CDIM, CDIM, 0);
}

// round 7
// speedup vs baseline: 1.7862x; 1.7862x over previous
#include <cuda_runtime.h>
#include <cuda_fp16.h>
#include <math.h>
#include <stdint.h>

#define TSEQ   2048
#define BATCH  2
#define CDIM   1024
#define NHEAD  16
#define HD     64
#define WIN    256
#define MROWS  (BATCH*TSEQ)   /* 4096 */

// Scratch (allocation-free rule: __device__ globals; uint16 = half storage)
static __device__ unsigned short g_q[(size_t)MROWS*CDIM];
static __device__ unsigned short g_k[(size_t)MROWS*CDIM];
static __device__ unsigned short g_v[(size_t)MROWS*CDIM];
static __device__ unsigned short g_y[(size_t)MROWS*CDIM];
static __device__ unsigned short g_xh[(size_t)MROWS*CDIM];
static __device__ unsigned short g_wh[4][(size_t)CDIM*CDIM];

// ===========================================================================
// PTX helpers
// ===========================================================================
__device__ __forceinline__ uint32_t smem_u32(const void* p) {
    uint32_t a;
    asm("{ .reg .u64 t; cvta.to.shared.u64 t, %1; cvt.u32.u64 %0, t; }" : "=r"(a) : "l"(p));
    return a;
}
__device__ __forceinline__ void cp_async16(uint32_t s, const void* g) {
    asm volatile("cp.async.cg.shared.global [%0], [%1], 16;" :: "r"(s), "l"(g) : "memory");
}
__device__ __forceinline__ void cp_commit() {
    asm volatile("cp.async.commit_group;" ::: "memory");
}
template <int N_>
__device__ __forceinline__ void cp_wait() {
    asm volatile("cp.async.wait_group %0;" :: "n"(N_) : "memory");
}
// D = A @ B + D ; fp16 in, fp32 accum
__device__ __forceinline__ void mma_f16(float* c, const uint32_t* a, const uint32_t* b) {
    asm volatile(
        "mma.sync.aligned.m16n8k16.row.col.f32.f16.f16.f32 "
        "{%0,%1,%2,%3}, {%4,%5,%6,%7}, {%8,%9}, {%0,%1,%2,%3};"
        : "+f"(c[0]), "+f"(c[1]), "+f"(c[2]), "+f"(c[3])
        : "r"(a[0]), "r"(a[1]), "r"(a[2]), "r"(a[3]), "r"(b[0]), "r"(b[1]));
}
__device__ __forceinline__ void ldmatrix_x4t(uint32_t& r0, uint32_t& r1,
                                             uint32_t& r2, uint32_t& r3, uint32_t addr) {
    asm volatile("ldmatrix.sync.aligned.m8n8.x4.trans.shared.b16 {%0,%1,%2,%3}, [%4];"
                 : "=r"(r0), "=r"(r1), "=r"(r2), "=r"(r3) : "r"(addr));
}

// ===========================================================================
// prepass: float -> half
// ===========================================================================
__global__ void cvt_half_kernel(const float* __restrict__ in, __half* __restrict__ out, int n4)
{
    int i = blockIdx.x * blockDim.x + threadIdx.x;
    if (i < n4) {
        float4 v = ((const float4*)in)[i];
        half2 h0 = __floats2half2_rn(v.x, v.y);
        half2 h1 = __floats2half2_rn(v.z, v.w);
        ((half2*)out)[2 * i]     = h0;
        ((half2*)out)[2 * i + 1] = h1;
    }
}

// ===========================================================================
// fp16 mma GEMM: Y = Xh @ Wh + bias.  Xh [M][K], Wh [K][N] (both half).
// CTA 128x128, BK=32, 8 warps (2M x 4N), warp tile 64x32.
// A frags: half2 LDS; B frags: ldmatrix.x4.trans from k-major rows.
// Output: Yh (half) if non-null, else Yf (float).
// ===========================================================================
#define BM 128
#define BN 128
#define BKH 32
#define ASTRH 40    /* halfs per A smem row: 20 banks/row -> conflict-free */
#define BSTRH 136   /* halfs per B smem row: 68 banks/row -> ldmatrix conflict-free */

__global__ __launch_bounds__(256, 2)
void gemm_h_kernel(const __half* __restrict__ X, const __half* __restrict__ W,
                   const float* __restrict__ bias, float* __restrict__ Yf,
                   __half* __restrict__ Yh, int M, int N, int K)
{
    __shared__ __align__(16) __half As[2][BM * ASTRH];
    __shared__ __align__(16) __half Bs[2][BKH * BSTRH];

    const int tid  = threadIdx.x;
    const int wid  = tid >> 5;
    const int lane = tid & 31;
    const int wm   = wid & 1;
    const int wn   = wid >> 1;
    const int m0 = blockIdx.y * BM;
    const int n0 = blockIdx.x * BN;
    const int grp = lane >> 2;
    const int qid = lane & 3;

    float c[4][4][4];
#pragma unroll
    for (int i = 0; i < 4; i++)
#pragma unroll
        for (int j = 0; j < 4; j++)
#pragma unroll
            for (int r = 0; r < 4; r++) c[i][j][r] = 0.f;

    // cp.async: A 512 txns (4/row of 64B), B 512 txns (16/row of 256B)
    const int ai[2] = { tid * 2, tid * 2 + 1 };
    const int arow[2] = { ai[0] >> 2, ai[1] >> 2 };
    const int aseg[2] = { ai[0] & 3,  ai[1] & 3 };
    const int brow[2] = { ai[0] >> 4, ai[1] >> 4 };
    const int bseg[2] = { ai[0] & 15, ai[1] & 15 };

    const uint32_t sA[2] = { smem_u32(As[0]), smem_u32(As[1]) };
    const uint32_t sB[2] = { smem_u32(Bs[0]), smem_u32(Bs[1]) };

#define LOAD_STAGE(st, k0)                                                        \
    do {                                                                          \
        _Pragma("unroll")                                                         \
        for (int q = 0; q < 2; q++)                                               \
            cp_async16(sA[st] + (uint32_t)(arow[q] * (ASTRH * 2) + aseg[q] * 16), \
                       &X[(size_t)(m0 + arow[q]) * K + (k0) + aseg[q] * 8]);      \
        _Pragma("unroll")                                                         \
        for (int q = 0; q < 2; q++)                                               \
            cp_async16(sB[st] + (uint32_t)(brow[q] * (BSTRH * 2) + bseg[q] * 16), \
                       &W[(size_t)((k0) + brow[q]) * N + n0 + bseg[q] * 8]);      \
        cp_commit();                                                              \
    } while (0)

    LOAD_STAGE(0, 0);

    const int NIT = K / BKH;   // 32
    for (int kt = 0; kt < NIT; kt++) {
        const int st = kt & 1;
        if (kt + 1 < NIT) {
            LOAD_STAGE(st ^ 1, (kt + 1) * BKH);
            cp_wait<1>();
        } else {
            cp_wait<0>();
        }
        __syncthreads();

        const __half* Ab = As[st];
        const uint32_t sBb = sB[st];
#pragma unroll
        for (int kk = 0; kk < 2; kk++) {
            const int kb = kk * 16;
            uint32_t af[4][4];
#pragma unroll
            for (int i = 0; i < 4; i++) {
                const int row = wm * 64 + i * 16 + grp;
                af[i][0] = *(const uint32_t*)&Ab[row * ASTRH + kb + 2 * qid];
                af[i][1] = *(const uint32_t*)&Ab[(row + 8) * ASTRH + kb + 2 * qid];
                af[i][2] = *(const uint32_t*)&Ab[row * ASTRH + kb + 2 * qid + 8];
                af[i][3] = *(const uint32_t*)&Ab[(row + 8) * ASTRH + kb + 2 * qid + 8];
            }
#pragma unroll
            for (int jp = 0; jp < 2; jp++) {
                const int col  = wn * 32 + jp * 16 + ((lane >> 4) << 3);
                const int krow = kb + (lane & 15);
                uint32_t b0, b1, b2, b3;
                ldmatrix_x4t(b0, b1, b2, b3,
                             sBb + (uint32_t)(krow * BSTRH + col) * 2);
                uint32_t bj0[2] = { b0, b1 };
                uint32_t bj1[2] = { b2, b3 };
#pragma unroll
                for (int i = 0; i < 4; i++) {
                    mma_f16(c[i][jp * 2],     af[i], bj0);
                    mma_f16(c[i][jp * 2 + 1], af[i], bj1);
                }
            }
        }
        __syncthreads();
    }

    // epilogue
#pragma unroll
    for (int i = 0; i < 4; i++) {
        const int row = m0 + wm * 64 + i * 16 + grp;
#pragma unroll
        for (int j = 0; j < 4; j++) {
            const int col = n0 + wn * 32 + j * 8 + 2 * qid;
            const float b0 = bias[col], b1 = bias[col + 1];
            const float o0 = c[i][j][0] + b0, o1 = c[i][j][1] + b1;
            const float o2 = c[i][j][2] + b0, o3 = c[i][j][3] + b1;
            if (Yh) {
                *(half2*)&Yh[(size_t)row * N + col]       = __floats2half2_rn(o0, o1);
                *(half2*)&Yh[(size_t)(row + 8) * N + col] = __floats2half2_rn(o2, o3);
            } else {
                float2 v0 = { o0, o1 }, v1 = { o2, o3 };
                *(float2*)&Yf[(size_t)row * N + col]       = v0;
                *(float2*)&Yf[(size_t)(row + 8) * N + col] = v1;
            }
        }
    }
#undef LOAD_STAGE
}

// ---------------------------------------------------------------------------
// Sliding-window flash attention, fp16 mma, fp32 softmax/accum.
// 8 warps; warp w: m16 rows (w&3)*16, n32 cols (w>>2)*32.
// ---------------------------------------------------------------------------
#define QSTRH 72
#define KSTRH 72
#define VSTRH 72
#define PSTRH 72
#define SSTR  68
#define ATT_SMEM_B (64 * (QSTRH + KSTRH + VSTRH + PSTRH) * 2 + 64 * SSTR * 4)

__global__ __launch_bounds__(256)
void attn_kernel(const __half* __restrict__ qg, const __half* __restrict__ kg,
                 const __half* __restrict__ vg, __half* __restrict__ yg)
{
    extern __shared__ __align__(16) char dsm[];
    __half* qs = (__half*)dsm;
    __half* ks = qs + 64 * QSTRH;
    __half* vs = ks + 64 * KSTRH;
    __half* ps = vs + 64 * VSTRH;
    float*  ss = (float*)(ps + 64 * PSTRH);
    __shared__ float mrow[64], lrow[64], arow[64];

    const int tid  = threadIdx.x;
    const int wid  = tid >> 5;
    const int lane = tid & 31;
    const int grp  = lane >> 2;
    const int qid  = lane & 3;
    const int mrow0 = (wid & 3) * 16;
    const int ncol0 = (wid >> 2) * 32;
    const uint32_t vs_u32 = smem_u32(vs);

    const int qt = blockIdx.x;
    const int h  = blockIdx.y;
    const int b  = blockIdx.z;
    const int q0 = qt * 64;
    const size_t base = ((size_t)b * TSEQ) * CDIM + (size_t)h * HD;

    for (int e = tid; e < 64 * 32; e += 256) {
        int r = e >> 5, c2 = e & 31;
        *(half2*)&qs[r * QSTRH + 2 * c2] =
            *(const half2*)&qg[base + (size_t)(q0 + r) * CDIM + 2 * c2];
    }
    if (tid < 64) { mrow[tid] = -INFINITY; lrow[tid] = 0.f; }

    float oacc[4][4];
#pragma unroll
    for (int j = 0; j < 4; j++)
#pragma unroll
        for (int r = 0; r < 4; r++) oacc[j][r] = 0.f;
    __syncthreads();

    const int kt_lo = (qt >= 4) ? (qt - 4) : 0;
    for (int kt = kt_lo; kt <= qt; kt++) {
        const int k0 = kt * 64;
        for (int e = tid; e < 64 * 32; e += 256) {
            int r = e >> 5, c2 = e & 31;
            *(half2*)&ks[r * KSTRH + 2 * c2] =
                *(const half2*)&kg[base + (size_t)(k0 + r) * CDIM + 2 * c2];
            *(half2*)&vs[r * VSTRH + 2 * c2] =
                *(const half2*)&vg[base + (size_t)(k0 + r) * CDIM + 2 * c2];
        }
        __syncthreads();

        // ---- S = Q K^T : 4 k16 steps ----
        float sacc[4][4];
#pragma unroll
        for (int j = 0; j < 4; j++)
#pragma unroll
            for (int r = 0; r < 4; r++) sacc[j][r] = 0.f;
#pragma unroll
        for (int ks16 = 0; ks16 < 4; ks16++) {
            const int kb = ks16 * 16;
            const int ra = mrow0 + grp;
            uint32_t af[4];
            af[0] = *(const uint32_t*)&qs[ra * QSTRH + kb + 2 * qid];
            af[1] = *(const uint32_t*)&qs[(ra + 8) * QSTRH + kb + 2 * qid];
            af[2] = *(const uint32_t*)&qs[ra * QSTRH + kb + 2 * qid + 8];
            af[3] = *(const uint32_t*)&qs[(ra + 8) * QSTRH + kb + 2 * qid + 8];
#pragma unroll
            for (int j = 0; j < 4; j++) {
                const int cn = ncol0 + j * 8 + grp;
                uint32_t bf[2];
                bf[0] = *(const uint32_t*)&ks[cn * KSTRH + kb + 2 * qid];
                bf[1] = *(const uint32_t*)&ks[cn * KSTRH + kb + 2 * qid + 8];
                mma_f16(sacc[j], af, bf);
            }
        }

        // ---- mask/scale specialized ----
        const int r0 = mrow0 + grp;
        if (kt == qt) {              // causal edge
#pragma unroll
            for (int j = 0; j < 4; j++) {
                const int col = ncol0 + j * 8 + 2 * qid;
                const int d0 = r0 - col;
                ss[r0 * SSTR + col]           = (d0 >= 0)  ? sacc[j][0] * 0.125f : -INFINITY;
                ss[r0 * SSTR + col + 1]       = (d0 >= 1)  ? sacc[j][1] * 0.125f : -INFINITY;
                ss[(r0 + 8) * SSTR + col]     = (d0 >= -8) ? sacc[j][2] * 0.125f : -INFINITY;
                ss[(r0 + 8) * SSTR + col + 1] = (d0 >= -7) ? sacc[j][3] * 0.125f : -INFINITY;
            }
        } else if (kt == qt - 4) {   // window edge
#pragma unroll
            for (int j = 0; j < 4; j++) {
                const int col = ncol0 + j * 8 + 2 * qid;
                const int d0 = (r0 + 256) - col;
                ss[r0 * SSTR + col]           = (d0 <= WIN)     ? sacc[j][0] * 0.125f : -INFINITY;
                ss[r0 * SSTR + col + 1]       = (d0 - 1 <= WIN) ? sacc[j][1] * 0.125f : -INFINITY;
                ss[(r0 + 8) * SSTR + col]     = (d0 + 8 <= WIN) ? sacc[j][2] * 0.125f : -INFINITY;
                ss[(r0 + 8) * SSTR + col + 1] = (d0 + 7 <= WIN) ? sacc[j][3] * 0.125f : -INFINITY;
            }
        } else {                     // interior
#pragma unroll
            for (int j = 0; j < 4; j++) {
                const int col = ncol0 + j * 8 + 2 * qid;
                ss[r0 * SSTR + col]           = sacc[j][0] * 0.125f;
                ss[r0 * SSTR + col + 1]       = sacc[j][1] * 0.125f;
                ss[(r0 + 8) * SSTR + col]     = sacc[j][2] * 0.125f;
                ss[(r0 + 8) * SSTR + col + 1] = sacc[j][3] * 0.125f;
            }
        }
        __syncthreads();

        // ---- online softmax (fp32), P -> half ----
        {
            const int row = tid >> 2, seg = tid & 3;
            float* srow = ss + row * SSTR + seg * 16;
            __half* prow = ps + row * PSTRH + seg * 16;
            float mloc = -INFINITY;
#pragma unroll
            for (int c2 = 0; c2 < 16; c2++) mloc = fmaxf(mloc, srow[c2]);
            mloc = fmaxf(mloc, __shfl_xor_sync(0xffffffffu, mloc, 1));
            mloc = fmaxf(mloc, __shfl_xor_sync(0xffffffffu, mloc, 2));
            const float mold = mrow[row];
            const float mnew = fmaxf(mold, mloc);
            const float al   = __expf(mold - mnew);
            float suml = 0.f;
#pragma unroll
            for (int c2 = 0; c2 < 16; c2 += 2) {
                float p0 = __expf(srow[c2] - mnew);
                float p1 = __expf(srow[c2 + 1] - mnew);
                suml += p0 + p1;
                *(half2*)&prow[c2] = __floats2half2_rn(p0, p1);
            }
            suml += __shfl_xor_sync(0xffffffffu, suml, 1);
            suml += __shfl_xor_sync(0xffffffffu, suml, 2);
            if (seg == 0) {
                mrow[row] = mnew;
                lrow[row] = lrow[row] * al + suml;
                arow[row] = al;
            }
        }
        __syncthreads();

        // ---- rescale O, O += P @ V ----
        {
            const float a_lo = arow[mrow0 + grp];
            const float a_hi = arow[mrow0 + grp + 8];
#pragma unroll
            for (int j = 0; j < 4; j++) {
                oacc[j][0] *= a_lo; oacc[j][1] *= a_lo;
                oacc[j][2] *= a_hi; oacc[j][3] *= a_hi;
            }
        }
#pragma unroll
        for (int ks16 = 0; ks16 < 4; ks16++) {
            const int kb = ks16 * 16;
            const int ra = mrow0 + grp;
            uint32_t af[4];
            af[0] = *(const uint32_t*)&ps[ra * PSTRH + kb + 2 * qid];
            af[1] = *(const uint32_t*)&ps[(ra + 8) * PSTRH + kb + 2 * qid];
            af[2] = *(const uint32_t*)&ps[ra * PSTRH + kb + 2 * qid + 8];
            af[3] = *(const uint32_t*)&ps[(ra + 8) * PSTRH + kb + 2 * qid + 8];
#pragma unroll
            for (int jp = 0; jp < 2; jp++) {
                const int col  = ncol0 + jp * 16 + ((lane >> 4) << 3);
                const int krow = kb + (lane & 15);
                uint32_t b0, b1, b2, b3;
                ldmatrix_x4t(b0, b1, b2, b3,
                             vs_u32 + (uint32_t)(krow * VSTRH + col) * 2);
                uint32_t bj0[2] = { b0, b1 };
                uint32_t bj1[2] = { b2, b3 };
                mma_f16(oacc[jp * 2],     af, bj0);
                mma_f16(oacc[jp * 2 + 1], af, bj1);
            }
        }
        __syncthreads();
    }

    // epilogue: normalize, write y (half)
    {
        const int r0 = mrow0 + grp;
        const float inv_lo = 1.0f / lrow[r0];
        const float inv_hi = 1.0f / lrow[r0 + 8];
#pragma unroll
        for (int j = 0; j < 4; j++) {
            const int col = ncol0 + j * 8 + 2 * qid;
            *(half2*)&yg[base + (size_t)(q0 + r0) * CDIM + col] =
                __floats2half2_rn(oacc[j][0] * inv_lo, oacc[j][1] * inv_lo);
            *(half2*)&yg[base + (size_t)(q0 + r0 + 8) * CDIM + col] =
                __floats2half2_rn(oacc[j][2] * inv_hi, oacc[j][3] * inv_hi);
        }
    }
}

// ---------------------------------------------------------------------------
extern "C" void kernel_launch(void* const* d_in, const int* in_sizes, int n_in,
                              void* d_out, int out_size)
{
    const float* x  = (const float*)d_in[0];
    const float* Wq = (const float*)d_in[1];
    const float* bq = (const float*)d_in[2];
    const float* Wk = (const float*)d_in[3];
    const float* bk = (const float*)d_in[4];
    const float* Wv = (const float*)d_in[5];
    const float* bv = (const float*)d_in[6];
    const float* Wo = (const float*)d_in[7];
    const float* bo = (const float*)d_in[8];
    float* out = (float*)d_out;
    (void)in_sizes; (void)n_in; (void)out_size;

    __half *qp, *kp, *vp, *yp, *xhp, *whp;
    cudaGetSymbolAddress((void**)&qp,  g_q);
    cudaGetSymbolAddress((void**)&kp,  g_k);
    cudaGetSymbolAddress((void**)&vp,  g_v);
    cudaGetSymbolAddress((void**)&yp,  g_y);
    cudaGetSymbolAddress((void**)&xhp, g_xh);
    cudaGetSymbolAddress((void**)&whp, g_wh);
    __half* whq = whp;
    __half* whk = whp + (size_t)CDIM * CDIM;
    __half* whv = whp + 2 * (size_t)CDIM * CDIM;
    __half* who = whp + 3 * (size_t)CDIM * CDIM;

    cudaFuncSetAttribute(attn_kernel,
                         cudaFuncAttributeMaxDynamicSharedMemorySize, ATT_SMEM_B);

    const int NX4 = MROWS * CDIM / 4;
    const int NW4 = CDIM * CDIM / 4;
    cvt_half_kernel<<<(NX4 + 255) / 256, 256>>>(x,  xhp, NX4);
    cvt_half_kernel<<<(NW4 + 255) / 256, 256>>>(Wq, whq, NW4);
    cvt_half_kernel<<<(NW4 + 255) / 256, 256>>>(Wk, whk, NW4);
    cvt_half_kernel<<<(NW4 + 255) / 256, 256>>>(Wv, whv, NW4);
    cvt_half_kernel<<<(NW4 + 255) / 256, 256>>>(Wo, who, NW4);

    dim3 ggrid(CDIM / BN, MROWS / BM);
    gemm_h_kernel<<<ggrid, 256>>>(xhp, whq, bq, nullptr, qp, MROWS, CDIM, CDIM);
    gemm_h_kernel<<<ggrid, 256>>>(xhp, whk, bk, nullptr, kp, MROWS, CDIM, CDIM);
    gemm_h_kernel<<<ggrid, 256>>>(xhp, whv, bv, nullptr, vp, MROWS, CDIM, CDIM);

    attn_kernel<<<dim3(TSEQ / 64, NHEAD, BATCH), 256, ATT_SMEM_B>>>(qp, kp, vp, yp);

    gemm_h_kernel<<<ggrid, 256>>>(yp, who, bo, out, nullptr, MROWS, CDIM, CDIM);
}